// round 1
// baseline (speedup 1.0000x reference)
#include <cuda_runtime.h>

#define NN 50000
#define EE 640000
#define HH 128
#define GG 128
#define FN 64
#define FEDGE 16
#define FLIG 200
#define FPOC 100
#define RPB 4   // node rows per block in conv kernels (50000 % 4 == 0)

// ---- scratch (no allocations allowed) ----
__device__ int   g_counts[NN];
__device__ int   g_fill[NN];
__device__ int   g_rowptr[NN + 1];
__device__ int   g_src[EE];
__device__ int   g_eid[EE];
__device__ float g_h0[NN * HH];
__device__ float g_h1[NN * HH];
__device__ float g_aedge[NN * FEDGE];
__device__ float g_pool[GG * HH];
__device__ float g_cnt[GG];

// ---- setup: zero per-call state ----
__global__ void k_zero() {
    int i = blockIdx.x * blockDim.x + threadIdx.x;
    if (i < NN) { g_counts[i] = 0; g_fill[i] = 0; }
    if (i < GG * HH) g_pool[i] = 0.f;
    if (i < GG) g_cnt[i] = 0.f;
}

// ---- CSR build: histogram of dst ----
__global__ void k_count(const int* __restrict__ ei) {
    int e = blockIdx.x * blockDim.x + threadIdx.x;
    if (e < EE) atomicAdd(&g_counts[ei[EE + e]], 1);
}

// ---- single-block exclusive scan over 50000 counts -> row_ptr ----
__global__ void k_scan() {
    __shared__ int ss[1024];
    int t = threadIdx.x;
    const int chunk = (NN + 1023) / 1024;   // 49
    int start = t * chunk;
    int end = min(start + chunk, NN);
    int s = 0;
    for (int i = start; i < end; i++) s += g_counts[i];
    ss[t] = s;
    __syncthreads();
    for (int off = 1; off < 1024; off <<= 1) {
        int v = (t >= off) ? ss[t - off] : 0;
        __syncthreads();
        ss[t] += v;
        __syncthreads();
    }
    int run = (t == 0) ? 0 : ss[t - 1];
    for (int i = start; i < end; i++) { g_rowptr[i] = run; run += g_counts[i]; }
    if (t == 1023) g_rowptr[NN] = ss[1023];
}

// ---- CSR fill: scatter edges into per-dst segments ----
__global__ void k_fill(const int* __restrict__ ei) {
    int e = blockIdx.x * blockDim.x + threadIdx.x;
    if (e >= EE) return;
    int d = ei[EE + e];
    int pos = g_rowptr[d] + atomicAdd(&g_fill[d], 1);
    g_src[pos] = ei[e];
    g_eid[pos] = e;
}

// ---- layer-invariant: aggregated raw edge_attr per dst node ----
__global__ void k_aedge(const float* __restrict__ ea) {
    int idx = blockIdx.x * blockDim.x + threadIdx.x;
    if (idx >= NN * FEDGE) return;
    int n = idx >> 4, j = idx & 15;
    int beg = g_rowptr[n], end = g_rowptr[n + 1];
    float a = 0.f;
    for (int s = beg; s < end; s++) a += ea[g_eid[s] * FEDGE + j];
    g_aedge[idx] = a;
}

// ---- conv1: fused gather-sum + [64->128] msg GEMM + [16->128] edge GEMM
//              + [64->128] self GEMM + bias + relu ----
__global__ void k_conv1(const float* __restrict__ x,
                        const float* __restrict__ Wm, const float* __restrict__ bm,
                        const float* __restrict__ We, const float* __restrict__ be,
                        const float* __restrict__ Ws, const float* __restrict__ bs) {
    int n0 = blockIdx.x * RPB;
    int j = threadIdx.x;
    __shared__ float ax[RPB][FN];
    __shared__ float xn[RPB][FN];
    __shared__ float ae[RPB][FEDGE];

    if (j < FN) {
        #pragma unroll
        for (int r = 0; r < RPB; r++) {
            int n = n0 + r;
            int beg = g_rowptr[n], end = g_rowptr[n + 1];
            float a = 0.f;
            for (int s = beg; s < end; s++) a += x[g_src[s] * FN + j];
            ax[r][j] = a;
            xn[r][j] = x[n * FN + j];
        }
    } else if (j < FN + FEDGE) {
        int jj = j - FN;
        #pragma unroll
        for (int r = 0; r < RPB; r++) ae[r][jj] = g_aedge[(n0 + r) * FEDGE + jj];
    }
    __syncthreads();

    float bmbe = bm[j] + be[j];
    float bsj = bs[j];
    float acc[RPB];
    #pragma unroll
    for (int r = 0; r < RPB; r++) {
        float deg = (float)(g_rowptr[n0 + r + 1] - g_rowptr[n0 + r]);
        acc[r] = bsj + deg * bmbe;
    }
    #pragma unroll 4
    for (int k = 0; k < FN; k++) {
        float w = Wm[k * HH + j];
        #pragma unroll
        for (int r = 0; r < RPB; r++) acc[r] += ax[r][k] * w;
    }
    #pragma unroll
    for (int k = 0; k < FEDGE; k++) {
        float w = We[k * HH + j];
        #pragma unroll
        for (int r = 0; r < RPB; r++) acc[r] += ae[r][k] * w;
    }
    #pragma unroll 4
    for (int k = 0; k < FN; k++) {
        float w = Ws[k * HH + j];
        #pragma unroll
        for (int r = 0; r < RPB; r++) acc[r] += xn[r][k] * w;
    }
    #pragma unroll
    for (int r = 0; r < RPB; r++)
        g_h0[(n0 + r) * HH + j] = fmaxf(acc[r], 0.f);
}

// ---- stacked layer: fused gather-sum + [128->128] GEMM + edge term + identity skip + relu ----
__global__ void k_layer(int l,
                        const float* __restrict__ Wkm, const float* __restrict__ bkm,
                        const float* __restrict__ Wke, const float* __restrict__ bke) {
    const float* __restrict__ hin  = (l & 1) ? g_h1 : g_h0;
    float* __restrict__ hout       = (l & 1) ? g_h0 : g_h1;
    const float* __restrict__ Wm = Wkm + l * HH * HH;
    const float* __restrict__ bm = bkm + l * HH;
    const float* __restrict__ We = Wke + l * FEDGE * HH;
    const float* __restrict__ be = bke + l * HH;

    int n0 = blockIdx.x * RPB;
    int j = threadIdx.x;
    __shared__ float ah[RPB][HH];
    __shared__ float ae[RPB][FEDGE];

    float selfv[RPB], deg[RPB];
    #pragma unroll
    for (int r = 0; r < RPB; r++) {
        int n = n0 + r;
        int beg = g_rowptr[n], end = g_rowptr[n + 1];
        float a = 0.f;
        for (int s = beg; s < end; s++) a += hin[g_src[s] * HH + j];
        ah[r][j] = a;
        selfv[r] = hin[n * HH + j];
        deg[r] = (float)(end - beg);
    }
    if (j < FEDGE) {
        #pragma unroll
        for (int r = 0; r < RPB; r++) ae[r][j] = g_aedge[(n0 + r) * FEDGE + j];
    }
    __syncthreads();

    float bmbe = bm[j] + be[j];
    float acc[RPB];
    #pragma unroll
    for (int r = 0; r < RPB; r++) acc[r] = selfv[r] + deg[r] * bmbe;

    #pragma unroll 8
    for (int k = 0; k < HH; k++) {
        float w = Wm[k * HH + j];
        #pragma unroll
        for (int r = 0; r < RPB; r++) acc[r] += ah[r][k] * w;
    }
    #pragma unroll
    for (int k = 0; k < FEDGE; k++) {
        float w = We[k * HH + j];
        #pragma unroll
        for (int r = 0; r < RPB; r++) acc[r] += ae[r][k] * w;
    }
    #pragma unroll
    for (int r = 0; r < RPB; r++)
        hout[(n0 + r) * HH + j] = fmaxf(acc[r], 0.f);
}

// ---- global mean pool (sums + counts) ----
__global__ void k_pool(const int* __restrict__ batch) {
    int idx = blockIdx.x * blockDim.x + threadIdx.x;
    if (idx >= NN * HH) return;
    int n = idx >> 7, j = idx & 127;
    int g = batch[n];
    atomicAdd(&g_pool[g * HH + j], g_h1[idx]);
    if (j == 0) atomicAdd(&g_cnt[g], 1.f);
}

// ---- head: pooled | lig@Wl | poc@Wp -> fuse @Wf -> @Wo -> out[G,1] ----
__global__ void k_head(const float* __restrict__ lig, const float* __restrict__ poc,
                       const float* __restrict__ Wl, const float* __restrict__ bl,
                       const float* __restrict__ Wp, const float* __restrict__ bp,
                       const float* __restrict__ Wf, const float* __restrict__ bf,
                       const float* __restrict__ Wo, const float* __restrict__ bo,
                       float* __restrict__ out) {
    int g = blockIdx.x, j = threadIdx.x;
    __shared__ float f[3 * HH];
    __shared__ float o[HH];
    float c = fmaxf(g_cnt[g], 1.f);
    f[j] = g_pool[g * HH + j] / c;
    float a = bl[j];
    #pragma unroll 4
    for (int k = 0; k < FLIG; k++) a += lig[g * FLIG + k] * Wl[k * HH + j];
    f[HH + j] = a;
    float b = bp[j];
    #pragma unroll 4
    for (int k = 0; k < FPOC; k++) b += poc[g * FPOC + k] * Wp[k * HH + j];
    f[2 * HH + j] = b;
    __syncthreads();
    float acc = bf[j];
    #pragma unroll 8
    for (int k = 0; k < 3 * HH; k++) acc += f[k] * Wf[k * HH + j];
    o[j] = acc * Wo[j];
    __syncthreads();
    for (int s = 64; s > 0; s >>= 1) {
        if (j < s) o[j] += o[j + s];
        __syncthreads();
    }
    if (j == 0) out[g] = o[0] + bo[0];
}

extern "C" void kernel_launch(void* const* d_in, const int* in_sizes, int n_in,
                              void* d_out, int out_size) {
    const float* x    = (const float*)d_in[0];
    const int*   ei   = (const int*)d_in[1];
    const float* ea   = (const float*)d_in[2];
    const int*   batch= (const int*)d_in[3];
    const float* lig  = (const float*)d_in[4];
    const float* poc  = (const float*)d_in[5];
    const float* W1m  = (const float*)d_in[6];
    const float* b1m  = (const float*)d_in[7];
    const float* W1e  = (const float*)d_in[8];
    const float* b1e  = (const float*)d_in[9];
    const float* W1s  = (const float*)d_in[10];
    const float* b1s  = (const float*)d_in[11];
    const float* Wkm  = (const float*)d_in[12];
    const float* bkm  = (const float*)d_in[13];
    const float* Wke  = (const float*)d_in[14];
    const float* bke  = (const float*)d_in[15];
    const float* Wl   = (const float*)d_in[16];
    const float* bl   = (const float*)d_in[17];
    const float* Wp   = (const float*)d_in[18];
    const float* bp   = (const float*)d_in[19];
    const float* Wf   = (const float*)d_in[20];
    const float* bf   = (const float*)d_in[21];
    const float* Wo   = (const float*)d_in[22];
    const float* bo   = (const float*)d_in[23];
    float* out = (float*)d_out;

    k_zero <<<(NN + 255) / 256, 256>>>();
    k_count<<<(EE + 255) / 256, 256>>>(ei);
    k_scan <<<1, 1024>>>();
    k_fill <<<(EE + 255) / 256, 256>>>(ei);
    k_aedge<<<(NN * FEDGE + 255) / 256, 256>>>(ea);
    k_conv1<<<NN / RPB, HH>>>(x, W1m, b1m, W1e, b1e, W1s, b1s);
    for (int l = 0; l < 3; l++)
        k_layer<<<NN / RPB, HH>>>(l, Wkm, bkm, Wke, bke);
    k_pool <<<(NN * HH + 255) / 256, 256>>>(batch);
    k_head <<<GG, HH>>>(lig, poc, Wl, bl, Wp, bp, Wf, bf, Wo, bo, out);
}

// round 2
// speedup vs baseline: 1.0247x; 1.0247x over previous
#include <cuda_runtime.h>

#define NN 50000
#define EE 640000
#define HH 128
#define GG 128
#define FN 64
#define FEDGE 16
#define FLIG 200
#define FPOC 100
#define RPB 8   // node rows per block (50000 % 8 == 0)

// ---- scratch (no allocations allowed) ----
__device__ int   g_counts[NN];
__device__ int   g_fill[NN];
__device__ int   g_rowptr[NN + 1];
__device__ int   g_src[EE];
__device__ int   g_eid[EE];
__device__ float g_h0[NN * HH];
__device__ float g_h1[NN * HH];
__device__ float g_aedge[NN * FEDGE];
__device__ float g_pool[GG * HH];
__device__ float g_cnt[GG];

// ---- setup: zero per-call state ----
__global__ void k_zero() {
    int i = blockIdx.x * blockDim.x + threadIdx.x;
    if (i < NN) { g_counts[i] = 0; g_fill[i] = 0; }
    if (i < GG * HH) g_pool[i] = 0.f;
    if (i < GG) g_cnt[i] = 0.f;
}

// ---- CSR build: histogram of dst ----
__global__ void k_count(const int* __restrict__ ei) {
    int e = blockIdx.x * blockDim.x + threadIdx.x;
    if (e < EE) atomicAdd(&g_counts[ei[EE + e]], 1);
}

// ---- single-block exclusive scan over 50000 counts -> row_ptr ----
__global__ void k_scan() {
    __shared__ int ss[1024];
    int t = threadIdx.x;
    const int chunk = (NN + 1023) / 1024;   // 49
    int start = t * chunk;
    int end = min(start + chunk, NN);
    int s = 0;
    for (int i = start; i < end; i++) s += g_counts[i];
    ss[t] = s;
    __syncthreads();
    for (int off = 1; off < 1024; off <<= 1) {
        int v = (t >= off) ? ss[t - off] : 0;
        __syncthreads();
        ss[t] += v;
        __syncthreads();
    }
    int run = (t == 0) ? 0 : ss[t - 1];
    for (int i = start; i < end; i++) { g_rowptr[i] = run; run += g_counts[i]; }
    if (t == 1023) g_rowptr[NN] = ss[1023];
}

// ---- CSR fill: scatter edges into per-dst segments ----
__global__ void k_fill(const int* __restrict__ ei) {
    int e = blockIdx.x * blockDim.x + threadIdx.x;
    if (e >= EE) return;
    int d = ei[EE + e];
    int pos = g_rowptr[d] + atomicAdd(&g_fill[d], 1);
    g_src[pos] = ei[e];
    g_eid[pos] = e;
}

// ---- conv1: fused gather-sum + aedge precompute + [64->128]x2 + [16->128] GEMMs + relu ----
__global__ void __launch_bounds__(HH) k_conv1(
        const float* __restrict__ x, const float* __restrict__ ea,
        const float* __restrict__ Wm, const float* __restrict__ bm,
        const float* __restrict__ We, const float* __restrict__ be,
        const float* __restrict__ Ws, const float* __restrict__ bs) {
    int n0 = blockIdx.x * RPB;
    int j = threadIdx.x;
    __shared__ float ax[RPB][FN];
    __shared__ float xn[RPB][FN];
    __shared__ float ae[RPB][FEDGE];

    if (j < FN) {
        // gather-sum of x over in-edges, column j, all RPB rows
        #pragma unroll
        for (int r = 0; r < RPB; r++) {
            int n = n0 + r;
            int beg = g_rowptr[n], end = g_rowptr[n + 1];
            float a0 = 0.f, a1 = 0.f;
            int s = beg;
            for (; s + 1 < end; s += 2) {
                a0 += x[g_src[s] * FN + j];
                a1 += x[g_src[s + 1] * FN + j];
            }
            if (s < end) a0 += x[g_src[s] * FN + j];
            ax[r][j] = a0 + a1;
        }
    } else {
        int jj = j - FN;
        #pragma unroll
        for (int r = 0; r < RPB; r++) xn[r][jj] = x[(n0 + r) * FN + jj];
        // aedge: 64 threads cover 8 rows x 16 cols exactly (one pair each)
        int col = jj & (FEDGE - 1);
        int r = jj >> 4;    // 0..3
        #pragma unroll
        for (int rr = 0; rr < 2; rr++) {
            int n = n0 + r * 2 + rr;
            int beg = g_rowptr[n], end = g_rowptr[n + 1];
            float a0 = 0.f, a1 = 0.f;
            int s = beg;
            for (; s + 1 < end; s += 2) {
                a0 += ea[g_eid[s] * FEDGE + col];
                a1 += ea[g_eid[s + 1] * FEDGE + col];
            }
            if (s < end) a0 += ea[g_eid[s] * FEDGE + col];
            float v = a0 + a1;
            ae[r * 2 + rr][col] = v;
            g_aedge[(n0 + r * 2 + rr) * FEDGE + col] = v;
        }
    }
    __syncthreads();

    float bmbe = bm[j] + be[j];
    float bsj = bs[j];
    float acc[RPB];
    #pragma unroll
    for (int r = 0; r < RPB; r++) {
        float deg = (float)(g_rowptr[n0 + r + 1] - g_rowptr[n0 + r]);
        acc[r] = bsj + deg * bmbe;
    }
    #pragma unroll 2
    for (int k = 0; k < FN; k++) {
        float wm = Wm[k * HH + j];
        float ws = Ws[k * HH + j];
        #pragma unroll
        for (int r = 0; r < RPB; r++) {
            acc[r] += ax[r][k] * wm;
            acc[r] += xn[r][k] * ws;
        }
    }
    #pragma unroll 2
    for (int k = 0; k < FEDGE; k++) {
        float w = We[k * HH + j];
        #pragma unroll
        for (int r = 0; r < RPB; r++) acc[r] += ae[r][k] * w;
    }
    #pragma unroll
    for (int r = 0; r < RPB; r++)
        g_h0[(n0 + r) * HH + j] = fmaxf(acc[r], 0.f);
}

// ---- stacked layer: fused gather-sum + [128->128] GEMM + edge term + skip + relu ----
__global__ void __launch_bounds__(HH) k_layer(int l,
                        const float* __restrict__ Wkm, const float* __restrict__ bkm,
                        const float* __restrict__ Wke, const float* __restrict__ bke) {
    const float* __restrict__ hin  = (l & 1) ? g_h1 : g_h0;
    float* __restrict__ hout       = (l & 1) ? g_h0 : g_h1;
    const float* __restrict__ Wm = Wkm + l * HH * HH;
    const float* __restrict__ bm = bkm + l * HH;
    const float* __restrict__ We = Wke + l * FEDGE * HH;
    const float* __restrict__ be = bke + l * HH;

    int n0 = blockIdx.x * RPB;
    int j = threadIdx.x;
    __shared__ float ah[RPB][HH];
    __shared__ float ae[RPB][FEDGE];

    float selfv[RPB], deg[RPB];
    #pragma unroll
    for (int r = 0; r < RPB; r++) {
        int n = n0 + r;
        int beg = g_rowptr[n], end = g_rowptr[n + 1];
        float a0 = 0.f, a1 = 0.f;
        int s = beg;
        for (; s + 1 < end; s += 2) {
            a0 += hin[g_src[s] * HH + j];
            a1 += hin[g_src[s + 1] * HH + j];
        }
        if (s < end) a0 += hin[g_src[s] * HH + j];
        ah[r][j] = a0 + a1;
        selfv[r] = hin[n * HH + j];
        deg[r] = (float)(end - beg);
    }
    if (j < RPB * FEDGE) {
        int r = j >> 4, col = j & (FEDGE - 1);
        ae[r][col] = g_aedge[(n0 + r) * FEDGE + col];
    }
    __syncthreads();

    float bmbe = bm[j] + be[j];
    float acc[RPB];
    #pragma unroll
    for (int r = 0; r < RPB; r++) acc[r] = selfv[r] + deg[r] * bmbe;

    #pragma unroll 2
    for (int k = 0; k < HH; k++) {
        float w = Wm[k * HH + j];
        #pragma unroll
        for (int r = 0; r < RPB; r++) acc[r] += ah[r][k] * w;
    }
    #pragma unroll 2
    for (int k = 0; k < FEDGE; k++) {
        float w = We[k * HH + j];
        #pragma unroll
        for (int r = 0; r < RPB; r++) acc[r] += ae[r][k] * w;
    }
    #pragma unroll
    for (int r = 0; r < RPB; r++)
        hout[(n0 + r) * HH + j] = fmaxf(acc[r], 0.f);
}

// ---- global mean pool (sums + counts) ----
__global__ void k_pool(const int* __restrict__ batch) {
    int idx = blockIdx.x * blockDim.x + threadIdx.x;
    if (idx >= NN * HH) return;
    int n = idx >> 7, j = idx & 127;
    int g = batch[n];
    atomicAdd(&g_pool[g * HH + j], g_h1[idx]);
    if (j == 0) atomicAdd(&g_cnt[g], 1.f);
}

// ---- head: pooled | lig@Wl | poc@Wp -> fuse @Wf -> @Wo -> out[G,1] ----
__global__ void k_head(const float* __restrict__ lig, const float* __restrict__ poc,
                       const float* __restrict__ Wl, const float* __restrict__ bl,
                       const float* __restrict__ Wp, const float* __restrict__ bp,
                       const float* __restrict__ Wf, const float* __restrict__ bf,
                       const float* __restrict__ Wo, const float* __restrict__ bo,
                       float* __restrict__ out) {
    int g = blockIdx.x, j = threadIdx.x;
    __shared__ float f[3 * HH];
    __shared__ float o[HH];
    float c = fmaxf(g_cnt[g], 1.f);
    f[j] = g_pool[g * HH + j] / c;
    float a = bl[j];
    #pragma unroll 4
    for (int k = 0; k < FLIG; k++) a += lig[g * FLIG + k] * Wl[k * HH + j];
    f[HH + j] = a;
    float b = bp[j];
    #pragma unroll 4
    for (int k = 0; k < FPOC; k++) b += poc[g * FPOC + k] * Wp[k * HH + j];
    f[2 * HH + j] = b;
    __syncthreads();
    float acc = bf[j];
    #pragma unroll 8
    for (int k = 0; k < 3 * HH; k++) acc += f[k] * Wf[k * HH + j];
    o[j] = acc * Wo[j];
    __syncthreads();
    for (int s = 64; s > 0; s >>= 1) {
        if (j < s) o[j] += o[j + s];
        __syncthreads();
    }
    if (j == 0) out[g] = o[0] + bo[0];
}

extern "C" void kernel_launch(void* const* d_in, const int* in_sizes, int n_in,
                              void* d_out, int out_size) {
    const float* x    = (const float*)d_in[0];
    const int*   ei   = (const int*)d_in[1];
    const float* ea   = (const float*)d_in[2];
    const int*   batch= (const int*)d_in[3];
    const float* lig  = (const float*)d_in[4];
    const float* poc  = (const float*)d_in[5];
    const float* W1m  = (const float*)d_in[6];
    const float* b1m  = (const float*)d_in[7];
    const float* W1e  = (const float*)d_in[8];
    const float* b1e  = (const float*)d_in[9];
    const float* W1s  = (const float*)d_in[10];
    const float* b1s  = (const float*)d_in[11];
    const float* Wkm  = (const float*)d_in[12];
    const float* bkm  = (const float*)d_in[13];
    const float* Wke  = (const float*)d_in[14];
    const float* bke  = (const float*)d_in[15];
    const float* Wl   = (const float*)d_in[16];
    const float* bl   = (const float*)d_in[17];
    const float* Wp   = (const float*)d_in[18];
    const float* bp   = (const float*)d_in[19];
    const float* Wf   = (const float*)d_in[20];
    const float* bf   = (const float*)d_in[21];
    const float* Wo   = (const float*)d_in[22];
    const float* bo   = (const float*)d_in[23];
    float* out = (float*)d_out;

    k_zero <<<(NN + 255) / 256, 256>>>();
    k_count<<<(EE + 255) / 256, 256>>>(ei);
    k_scan <<<1, 1024>>>();
    k_fill <<<(EE + 255) / 256, 256>>>(ei);
    k_conv1<<<NN / RPB, HH>>>(x, ea, W1m, b1m, W1e, b1e, W1s, b1s);
    for (int l = 0; l < 3; l++)
        k_layer<<<NN / RPB, HH>>>(l, Wkm, bkm, Wke, bke);
    k_pool <<<(NN * HH + 255) / 256, 256>>>(batch);
    k_head <<<GG, HH>>>(lig, poc, Wl, bl, Wp, bp, Wf, bf, Wo, bo, out);
}

// round 3
// speedup vs baseline: 1.1493x; 1.1216x over previous
#include <cuda_runtime.h>

#define NN 50000
#define EE 640000
#define HH 128
#define GG 128
#define FN 64
#define FEDGE 16
#define FLIG 200
#define FPOC 100
#define RPB 8     // rows per block (50000 % 8 == 0)
#define PAD 10    // transposed-tile row stride (even -> LDS.64 aligned)

// ---- scratch (zero-initialized at load; graph is self-restoring) ----
__device__ int   g_counts[NN];      // reset by k_fill
__device__ int   g_fill[NN];        // reset by k_conv1
__device__ int   g_rowptr[NN + 1];
__device__ int   g_src[EE];
__device__ int   g_eid[EE];
__device__ float g_h0[NN * HH];
__device__ float g_h1[NN * HH];
__device__ float g_aedge[NN * FEDGE];
__device__ float g_pool[GG * HH];

// ---- f32x2 packed helpers ----
__device__ __forceinline__ unsigned long long pk2(float lo, float hi) {
    unsigned long long r;
    asm("mov.b64 %0, {%1, %2};" : "=l"(r) : "f"(lo), "f"(hi));
    return r;
}
__device__ __forceinline__ float2 upk2(unsigned long long v) {
    float2 r; asm("mov.b64 {%0, %1}, %2;" : "=f"(r.x), "=f"(r.y) : "l"(v));
    return r;
}
__device__ __forceinline__ void fma2(unsigned long long& acc,
                                     unsigned long long a, unsigned long long b) {
    asm("fma.rn.f32x2 %0, %1, %2, %0;" : "+l"(acc) : "l"(a), "l"(b));
}

__device__ __forceinline__ int lbound(const int* __restrict__ arr, int n, int v) {
    int lo = 0, hi = n;
    while (lo < hi) { int m = (lo + hi) >> 1; if (arr[m] < v) lo = m + 1; else hi = m; }
    return lo;
}

// ---- CSR build: histogram of dst (int4 vectorized) ----
__global__ void k_count(const int* __restrict__ ei) {
    int t = blockIdx.x * blockDim.x + threadIdx.x;
    if (t >= EE / 4) return;
    int4 d = ((const int4*)(ei + EE))[t];
    atomicAdd(&g_counts[d.x], 1);
    atomicAdd(&g_counts[d.y], 1);
    atomicAdd(&g_counts[d.z], 1);
    atomicAdd(&g_counts[d.w], 1);
}

// ---- single-block exclusive scan over 50000 counts -> row_ptr ----
__global__ void k_scan() {
    __shared__ int ss[1024];
    int t = threadIdx.x;
    const int chunk = (NN + 1023) / 1024;
    int start = t * chunk;
    int end = min(start + chunk, NN);
    int s = 0;
    for (int i = start; i < end; i++) s += g_counts[i];
    ss[t] = s;
    __syncthreads();
    for (int off = 1; off < 1024; off <<= 1) {
        int v = (t >= off) ? ss[t - off] : 0;
        __syncthreads();
        ss[t] += v;
        __syncthreads();
    }
    int run = (t == 0) ? 0 : ss[t - 1];
    for (int i = start; i < end; i++) { g_rowptr[i] = run; run += g_counts[i]; }
    if (t == 1023) g_rowptr[NN] = ss[1023];
}

// ---- CSR fill (int4) + reset g_counts for next graph replay ----
__global__ void k_fill(const int* __restrict__ ei) {
    int t = blockIdx.x * blockDim.x + threadIdx.x;
    if (t >= EE / 4) return;
    int4 d = ((const int4*)(ei + EE))[t];
    int4 s = ((const int4*)ei)[t];
    int e = 4 * t;
    int p;
    p = g_rowptr[d.x] + atomicAdd(&g_fill[d.x], 1); g_src[p] = s.x; g_eid[p] = e;
    p = g_rowptr[d.y] + atomicAdd(&g_fill[d.y], 1); g_src[p] = s.y; g_eid[p] = e + 1;
    p = g_rowptr[d.z] + atomicAdd(&g_fill[d.z], 1); g_src[p] = s.z; g_eid[p] = e + 2;
    p = g_rowptr[d.w] + atomicAdd(&g_fill[d.w], 1); g_src[p] = s.w; g_eid[p] = e + 3;
    g_counts[d.x] = 0; g_counts[d.y] = 0; g_counts[d.z] = 0; g_counts[d.w] = 0;
}

// ---- conv1: warp-per-row gather + aedge + f32x2 GEMM ([64+64+16] -> 128) ----
__global__ void __launch_bounds__(256) k_conv1(
        const float* __restrict__ x, const float* __restrict__ ea,
        const float* __restrict__ Wm, const float* __restrict__ bm,
        const float* __restrict__ We, const float* __restrict__ be,
        const float* __restrict__ Ws, const float* __restrict__ bs) {
    int n0 = blockIdx.x * RPB;
    int tid = threadIdx.x;
    int warp = tid >> 5, lane = tid & 31;
    __shared__ float axT[FN][PAD];
    __shared__ float xnT[FN][PAD];
    __shared__ float aeT[FEDGE][PAD];
    __shared__ float sdeg[RPB];

    // -------- gather phase: warp r owns node n0+r --------
    {
        int n = n0 + warp;
        int beg = g_rowptr[n], end = g_rowptr[n + 1];
        int half = lane >> 4, hl = lane & 15;
        const float4* xb = (const float4*)x;

        // ax: two edges per warp step, 2-deep unroll (4 edges in flight)
        float4 a0 = make_float4(0.f, 0.f, 0.f, 0.f), a1 = a0;
        int s = beg;
        for (; s + 3 < end; s += 4) {
            float4 v0 = xb[g_src[s + half] * (FN / 4) + hl];
            float4 v1 = xb[g_src[s + 2 + half] * (FN / 4) + hl];
            a0.x += v0.x; a0.y += v0.y; a0.z += v0.z; a0.w += v0.w;
            a1.x += v1.x; a1.y += v1.y; a1.z += v1.z; a1.w += v1.w;
        }
        for (; s + 1 < end; s += 2) {
            float4 v = xb[g_src[s + half] * (FN / 4) + hl];
            a0.x += v.x; a0.y += v.y; a0.z += v.z; a0.w += v.w;
        }
        if (s < end && half == 0) {
            float4 v = xb[g_src[s] * (FN / 4) + hl];
            a0.x += v.x; a0.y += v.y; a0.z += v.z; a0.w += v.w;
        }
        a0.x += a1.x; a0.y += a1.y; a0.z += a1.z; a0.w += a1.w;
        a0.x += __shfl_xor_sync(0xffffffffu, a0.x, 16);
        a0.y += __shfl_xor_sync(0xffffffffu, a0.y, 16);
        a0.z += __shfl_xor_sync(0xffffffffu, a0.z, 16);
        a0.w += __shfl_xor_sync(0xffffffffu, a0.w, 16);
        if (half == 0) {
            axT[4 * hl + 0][warp] = a0.x;
            axT[4 * hl + 1][warp] = a0.y;
            axT[4 * hl + 2][warp] = a0.z;
            axT[4 * hl + 3][warp] = a0.w;
        } else {
            float4 v = xb[n * (FN / 4) + hl];
            xnT[4 * hl + 0][warp] = v.x;
            xnT[4 * hl + 1][warp] = v.y;
            xnT[4 * hl + 2][warp] = v.z;
            xnT[4 * hl + 3][warp] = v.w;
        }
        if (lane == 0) sdeg[warp] = (float)(end - beg);

        // aedge: 8 edges per warp step (lane L -> edge s + L/4, quarter L%4)
        float4 ac = make_float4(0.f, 0.f, 0.f, 0.f);
        int q = lane & 3;
        for (int t2 = beg; t2 < end; t2 += 8) {
            int e = t2 + (lane >> 2);
            if (e < end) {
                float4 v = ((const float4*)(ea + g_eid[e] * FEDGE))[q];
                ac.x += v.x; ac.y += v.y; ac.z += v.z; ac.w += v.w;
            }
        }
        #pragma unroll
        for (int m = 4; m <= 16; m <<= 1) {
            ac.x += __shfl_xor_sync(0xffffffffu, ac.x, m);
            ac.y += __shfl_xor_sync(0xffffffffu, ac.y, m);
            ac.z += __shfl_xor_sync(0xffffffffu, ac.z, m);
            ac.w += __shfl_xor_sync(0xffffffffu, ac.w, m);
        }
        if (lane < 4) {
            aeT[4 * q + 0][warp] = ac.x;
            aeT[4 * q + 1][warp] = ac.y;
            aeT[4 * q + 2][warp] = ac.z;
            aeT[4 * q + 3][warp] = ac.w;
            ((float4*)(g_aedge + n * FEDGE))[q] = ac;
        }
        // reset g_fill for next replay
        if (warp == 0 && lane < RPB) g_fill[n0 + lane] = 0;
    }
    __syncthreads();

    // -------- GEMM phase: 256 threads, col j x 4 rows each --------
    int j = tid & 127, rbase = (tid >> 7) * 4;
    float bmbe = bm[j] + be[j];
    float bsj = bs[j];
    float i0 = bsj + sdeg[rbase + 0] * bmbe;
    float i1 = bsj + sdeg[rbase + 1] * bmbe;
    float i2 = bsj + sdeg[rbase + 2] * bmbe;
    float i3 = bsj + sdeg[rbase + 3] * bmbe;
    unsigned long long acc01 = pk2(i0, i1), acc23 = pk2(i2, i3);

    #pragma unroll 16
    for (int k = 0; k < FN; k++) {
        float w = Wm[k * HH + j];
        unsigned long long ww = pk2(w, w);
        fma2(acc01, *(const unsigned long long*)&axT[k][rbase], ww);
        fma2(acc23, *(const unsigned long long*)&axT[k][rbase + 2], ww);
        float w2 = Ws[k * HH + j];
        unsigned long long ww2 = pk2(w2, w2);
        fma2(acc01, *(const unsigned long long*)&xnT[k][rbase], ww2);
        fma2(acc23, *(const unsigned long long*)&xnT[k][rbase + 2], ww2);
    }
    #pragma unroll
    for (int k = 0; k < FEDGE; k++) {
        float w = We[k * HH + j];
        unsigned long long ww = pk2(w, w);
        fma2(acc01, *(const unsigned long long*)&aeT[k][rbase], ww);
        fma2(acc23, *(const unsigned long long*)&aeT[k][rbase + 2], ww);
    }
    float2 r01 = upk2(acc01), r23 = upk2(acc23);
    g_h0[(n0 + rbase + 0) * HH + j] = fmaxf(r01.x, 0.f);
    g_h0[(n0 + rbase + 1) * HH + j] = fmaxf(r01.y, 0.f);
    g_h0[(n0 + rbase + 2) * HH + j] = fmaxf(r23.x, 0.f);
    g_h0[(n0 + rbase + 3) * HH + j] = fmaxf(r23.y, 0.f);
}

// ---- stacked layer: warp-per-row float4 gather + f32x2 GEMM [128->128] ----
__global__ void __launch_bounds__(256) k_layer(int l,
                        const float* __restrict__ Wkm, const float* __restrict__ bkm,
                        const float* __restrict__ Wke, const float* __restrict__ bke) {
    const float* __restrict__ hin  = (l & 1) ? g_h1 : g_h0;
    float* __restrict__ hout       = (l & 1) ? g_h0 : g_h1;
    const float* __restrict__ Wm = Wkm + l * HH * HH;
    const float* __restrict__ bm = bkm + l * HH;
    const float* __restrict__ We = Wke + l * FEDGE * HH;
    const float* __restrict__ be = bke + l * HH;

    int n0 = blockIdx.x * RPB;
    int tid = threadIdx.x;
    int warp = tid >> 5, lane = tid & 31;
    __shared__ float ahT[HH][PAD];
    __shared__ float aeT[FEDGE][PAD];
    __shared__ float sdeg[RPB];

    // -------- gather: warp r owns node n0+r, lane covers cols 4L..4L+3 --------
    {
        int n = n0 + warp;
        int beg = g_rowptr[n], end = g_rowptr[n + 1];
        const float4* hb = (const float4*)hin;
        float4 a0 = make_float4(0.f, 0.f, 0.f, 0.f), a1 = a0, a2 = a0, a3 = a0;
        int s = beg;
        for (; s + 3 < end; s += 4) {
            float4 v0 = hb[g_src[s] * (HH / 4) + lane];
            float4 v1 = hb[g_src[s + 1] * (HH / 4) + lane];
            float4 v2 = hb[g_src[s + 2] * (HH / 4) + lane];
            float4 v3 = hb[g_src[s + 3] * (HH / 4) + lane];
            a0.x += v0.x; a0.y += v0.y; a0.z += v0.z; a0.w += v0.w;
            a1.x += v1.x; a1.y += v1.y; a1.z += v1.z; a1.w += v1.w;
            a2.x += v2.x; a2.y += v2.y; a2.z += v2.z; a2.w += v2.w;
            a3.x += v3.x; a3.y += v3.y; a3.z += v3.z; a3.w += v3.w;
        }
        for (; s < end; s++) {
            float4 v = hb[g_src[s] * (HH / 4) + lane];
            a0.x += v.x; a0.y += v.y; a0.z += v.z; a0.w += v.w;
        }
        a0.x += a1.x + a2.x + a3.x;
        a0.y += a1.y + a2.y + a3.y;
        a0.z += a1.z + a2.z + a3.z;
        a0.w += a1.w + a2.w + a3.w;
        ahT[4 * lane + 0][warp] = a0.x;
        ahT[4 * lane + 1][warp] = a0.y;
        ahT[4 * lane + 2][warp] = a0.z;
        ahT[4 * lane + 3][warp] = a0.w;
        if (lane == 0) sdeg[warp] = (float)(end - beg);
        if (lane < 4) {
            float4 e = ((const float4*)(g_aedge + n * FEDGE))[lane];
            aeT[4 * lane + 0][warp] = e.x;
            aeT[4 * lane + 1][warp] = e.y;
            aeT[4 * lane + 2][warp] = e.z;
            aeT[4 * lane + 3][warp] = e.w;
        }
    }
    __syncthreads();

    // -------- GEMM: col j x 4 rows --------
    int j = tid & 127, rbase = (tid >> 7) * 4;
    float bmbe = bm[j] + be[j];
    float s0 = hin[(n0 + rbase + 0) * HH + j];
    float s1 = hin[(n0 + rbase + 1) * HH + j];
    float s2 = hin[(n0 + rbase + 2) * HH + j];
    float s3 = hin[(n0 + rbase + 3) * HH + j];
    unsigned long long acc01 = pk2(s0 + sdeg[rbase + 0] * bmbe, s1 + sdeg[rbase + 1] * bmbe);
    unsigned long long acc23 = pk2(s2 + sdeg[rbase + 2] * bmbe, s3 + sdeg[rbase + 3] * bmbe);

    #pragma unroll 16
    for (int k = 0; k < HH; k++) {
        float w = Wm[k * HH + j];
        unsigned long long ww = pk2(w, w);
        fma2(acc01, *(const unsigned long long*)&ahT[k][rbase], ww);
        fma2(acc23, *(const unsigned long long*)&ahT[k][rbase + 2], ww);
    }
    #pragma unroll
    for (int k = 0; k < FEDGE; k++) {
        float w = We[k * HH + j];
        unsigned long long ww = pk2(w, w);
        fma2(acc01, *(const unsigned long long*)&aeT[k][rbase], ww);
        fma2(acc23, *(const unsigned long long*)&aeT[k][rbase + 2], ww);
    }
    float2 r01 = upk2(acc01), r23 = upk2(acc23);
    hout[(n0 + rbase + 0) * HH + j] = fmaxf(r01.x, 0.f);
    hout[(n0 + rbase + 1) * HH + j] = fmaxf(r01.y, 0.f);
    hout[(n0 + rbase + 2) * HH + j] = fmaxf(r23.x, 0.f);
    hout[(n0 + rbase + 3) * HH + j] = fmaxf(r23.y, 0.f);
}

// ---- mean pool: batch is sorted -> binary-search segment, no atomics ----
__global__ void __launch_bounds__(256) k_pool(const int* __restrict__ batch) {
    int g = blockIdx.x;
    int tid = threadIdx.x;
    int j = tid & 127, half = tid >> 7;
    int lo = lbound(batch, NN, g);
    int hi = lbound(batch, NN, g + 1);
    float a = 0.f, b = 0.f;
    int n = lo + half;
    for (; n + 3 < hi; n += 4) {
        a += g_h1[n * HH + j];
        b += g_h1[(n + 2) * HH + j];
    }
    for (; n < hi; n += 2) a += g_h1[n * HH + j];
    __shared__ float red[256];
    red[tid] = a + b;
    __syncthreads();
    if (half == 0) {
        float s = red[j] + red[j + 128];
        float c = (float)(hi - lo);
        g_pool[g * HH + j] = s / fmaxf(c, 1.f);
    }
}

// ---- head ----
__global__ void k_head(const float* __restrict__ lig, const float* __restrict__ poc,
                       const float* __restrict__ Wl, const float* __restrict__ bl,
                       const float* __restrict__ Wp, const float* __restrict__ bp,
                       const float* __restrict__ Wf, const float* __restrict__ bf,
                       const float* __restrict__ Wo, const float* __restrict__ bo,
                       float* __restrict__ out) {
    int g = blockIdx.x, j = threadIdx.x;
    __shared__ float f[3 * HH];
    __shared__ float o[HH];
    f[j] = g_pool[g * HH + j];
    float a = bl[j];
    #pragma unroll 4
    for (int k = 0; k < FLIG; k++) a += lig[g * FLIG + k] * Wl[k * HH + j];
    f[HH + j] = a;
    float b = bp[j];
    #pragma unroll 4
    for (int k = 0; k < FPOC; k++) b += poc[g * FPOC + k] * Wp[k * HH + j];
    f[2 * HH + j] = b;
    __syncthreads();
    float acc = bf[j];
    #pragma unroll 8
    for (int k = 0; k < 3 * HH; k++) acc += f[k] * Wf[k * HH + j];
    o[j] = acc * Wo[j];
    __syncthreads();
    for (int s = 64; s > 0; s >>= 1) {
        if (j < s) o[j] += o[j + s];
        __syncthreads();
    }
    if (j == 0) out[g] = o[0] + bo[0];
}

extern "C" void kernel_launch(void* const* d_in, const int* in_sizes, int n_in,
                              void* d_out, int out_size) {
    const float* x    = (const float*)d_in[0];
    const int*   ei   = (const int*)d_in[1];
    const float* ea   = (const float*)d_in[2];
    const int*   batch= (const int*)d_in[3];
    const float* lig  = (const float*)d_in[4];
    const float* poc  = (const float*)d_in[5];
    const float* W1m  = (const float*)d_in[6];
    const float* b1m  = (const float*)d_in[7];
    const float* W1e  = (const float*)d_in[8];
    const float* b1e  = (const float*)d_in[9];
    const float* W1s  = (const float*)d_in[10];
    const float* b1s  = (const float*)d_in[11];
    const float* Wkm  = (const float*)d_in[12];
    const float* bkm  = (const float*)d_in[13];
    const float* Wke  = (const float*)d_in[14];
    const float* bke  = (const float*)d_in[15];
    const float* Wl   = (const float*)d_in[16];
    const float* bl   = (const float*)d_in[17];
    const float* Wp   = (const float*)d_in[18];
    const float* bp   = (const float*)d_in[19];
    const float* Wf   = (const float*)d_in[20];
    const float* bf   = (const float*)d_in[21];
    const float* Wo   = (const float*)d_in[22];
    const float* bo   = (const float*)d_in[23];
    float* out = (float*)d_out;

    k_count<<<(EE / 4 + 255) / 256, 256>>>(ei);                    // launch 0
    k_scan <<<1, 1024>>>();                                        // launch 1
    k_fill <<<(EE / 4 + 255) / 256, 256>>>(ei);                    // launch 2
    k_conv1<<<NN / RPB, 256>>>(x, ea, W1m, b1m, W1e, b1e, W1s, b1s); // launch 3 (profiled)
    for (int l = 0; l < 3; l++)
        k_layer<<<NN / RPB, 256>>>(l, Wkm, bkm, Wke, bke);         // 4,5,6
    k_pool <<<GG, 256>>>(batch);                                   // 7
    k_head <<<GG, HH>>>(lig, poc, Wl, bl, Wp, bp, Wf, bf, Wo, bo, out); // 8
}